// round 4
// baseline (speedup 1.0000x reference)
#include <cuda_runtime.h>
#include <math.h>

// RoIAlign_withBanks: N=2000 boxes, C=256, G=7, 6 FPN levels, dims {38,19,10,5,3,1}.
// Output [N, C, 7, 7] fp32.
//
// R4: dedup-gather design. The 7x7 grid over a level-matched box touches only
// UXn x UYn <= 14x14 (typically ~4x4) DISTINCT fmap elements per channel.
// Per box: build unique X/Y coord sets (bitmask + popcount ranks), then per
// 32-channel chunk gather the compact patch into shared (coalesced LDG/STS)
// and bilinear-sample from shared. TPB=196: each thread owns a fixed cell
// (pos = t % 49); weights + patch offsets live in registers; stores coalesced.

#define G_POOL 7
#define CELLS 49
#define NCH 256
#define TPB 196                 // = 4 * 49
#define CH 32                   // channels per chunk
#define CHUNKS (NCH / CH)       // 8
#define PATCH_MAX 196           // 14 x 14 worst case
#define CHUNK_ELEMS (CH * CELLS) // 1568 = 8 * 196

__device__ __forceinline__ int nth_set_bit(unsigned long long m, int n) {
    for (int k = 0; k < n; ++k) m &= m - 1;   // clear n lowest set bits
    return __ffsll(m) - 1;
}

__global__ __launch_bounds__(TPB) void roialign_banks_kernel(
    const float* __restrict__ boxes,
    const float* __restrict__ f0, const float* __restrict__ f1,
    const float* __restrict__ f2, const float* __restrict__ f3,
    const float* __restrict__ f4, const float* __restrict__ f5,
    float* __restrict__ out)
{
    __shared__ float s_patch[CH * PATCH_MAX];   // 25088 B
    __shared__ int   s_gidx[PATCH_MAX];         // plane-element offset per patch slot
    __shared__ int   s_ix0[G_POOL], s_ix1[G_POOL], s_iy0[G_POOL], s_iy1[G_POOL];
    __shared__ float s_px0[G_POOL], s_py0[G_POOL];
    __shared__ unsigned long long s_mx, s_my;
    __shared__ int s_UYn, s_P, s_q, s_r;

    const int n = blockIdx.x;
    const int t = threadIdx.x;

    const float bx1 = boxes[4 * n + 0];
    const float by1 = boxes[4 * n + 1];
    const float bx2 = boxes[4 * n + 2];
    const float by2 = boxes[4 * n + 3];

    // Level: clip(floor(5 + log2(sqrt(w*h))), 0, 5)
    const float avg = sqrtf((bx2 - bx1) * (by2 - by1));
    const float lf  = floorf(5.0f + log2f(avg));
    const int lvl   = (int)fminf(fmaxf(lf, 0.0f), 5.0f);

    const float* fm;
    int D;
    switch (lvl) {
        case 0:  fm = f0; D = 38; break;
        case 1:  fm = f1; D = 19; break;
        case 2:  fm = f2; D = 10; break;
        case 3:  fm = f3; D = 5;  break;
        case 4:  fm = f4; D = 3;  break;
        default: fm = f5; D = 1;  break;
    }
    const int DD = D * D;

    // --- grid coords along each axis (two warps work concurrently) ---
    if (t < G_POOL) {
        float xr = fminf(fmaxf(bx1 + (float)t * (bx2 - bx1) / 6.0f, 0.0f), 1.0f);
        float ux = xr * (float)(D - 1);
        float fx = floorf(ux);
        s_ix0[t] = (int)fx;
        s_ix1[t] = (int)ceilf(ux);
        s_px0[t] = 1.0f - (ux - fx);     // ddx trick: ceil-floor in {0,1} -> dd=1
    } else if (t >= 32 && t < 32 + G_POOL) {
        int j = t - 32;
        float yr = fminf(fmaxf(by1 + (float)j * (by2 - by1) / 6.0f, 0.0f), 1.0f);
        float uy = yr * (float)(D - 1);
        float fy = floorf(uy);
        s_iy0[j] = (int)fy;
        s_iy1[j] = (int)ceilf(uy);
        s_py0[j] = 1.0f - (uy - fy);
    }
    __syncthreads();

    // --- unique-coord masks + patch dims (one thread; tiny) ---
    if (t == 0) {
        unsigned long long mx = 0ull, my = 0ull;
#pragma unroll
        for (int i = 0; i < G_POOL; ++i) {
            mx |= (1ull << s_ix0[i]) | (1ull << s_ix1[i]);
            my |= (1ull << s_iy0[i]) | (1ull << s_iy1[i]);
        }
        s_mx = mx; s_my = my;
        int UYn = __popcll(my);
        int P   = __popcll(mx) * UYn;
        s_UYn = UYn; s_P = P;
        s_q = TPB / P; s_r = TPB % P;    // gather-cursor carry constants
    }
    __syncthreads();

    const unsigned long long mx = s_mx, my = s_my;
    const int UYn = s_UYn, P = s_P, q = s_q, r = s_r;

    // --- patch gather index table: slot p=(u,v) -> plane offset X[u]*D + Y[v]
    if (t < P) {
        int u = t / UYn, v = t - u * UYn;
        s_gidx[t] = nth_set_bit(mx, u) * D + nth_set_bit(my, v);
    }

    // --- per-thread cell meta (registers only) ---
    const int c0  = t / CELLS;           // 0..3
    const int pos = t - c0 * CELLS;
    {
    }
    const int i = pos / G_POOL, j = pos - (pos / G_POOL) * G_POOL;
    const int ix0 = s_ix0[i], ix1 = s_ix1[i];
    const int iy0 = s_iy0[j], iy1 = s_iy1[j];
    const float px0 = s_px0[i], py0 = s_py0[j];
    const int a0 = __popcll(mx & ((1ull << ix0) - 1ull));
    const int a1 = __popcll(mx & ((1ull << ix1) - 1ull));
    const int b0 = __popcll(my & ((1ull << iy0) - 1ull));
    const int b1 = __popcll(my & ((1ull << iy1) - 1ull));
    const int o00 = a0 * UYn + b0, o10 = a1 * UYn + b0;
    const int o01 = a0 * UYn + b1, o11 = a1 * UYn + b1;
    const float px1 = 1.0f - px0, py1 = 1.0f - py0;
    const float w00 = px0 * py0, w10 = px1 * py0;
    const float w01 = px0 * py1, w11 = px1 * py1;

    // gather cursor init for this thread (k = c*P + p, k starts at t)
    int gc0 = t / P;
    int gp0 = t - gc0 * P;

    __syncthreads();   // s_gidx ready

    const float* fmc = fm;                       // chunk base (channel 0 of chunk)
    float* op = out + (size_t)n * (NCH * CELLS) + t;
    const int NT = CH * P;                       // patch words per chunk
    const int P4 = P;                            // float stride per channel in patch

    for (int chunk = 0; chunk < CHUNKS; ++chunk) {
        // ---- gather compact patch: s_patch[k] = fm[c*DD + gidx[p]], k=c*P+p
        {
            int k = t, c = gc0, p = gp0;
            while (k < NT) {
                s_patch[k] = __ldg(fmc + c * DD + s_gidx[p]);
                k += TPB; c += q; p += r;
                if (p >= P) { p -= P; ++c; }
            }
        }
        __syncthreads();

        // ---- sample: thread covers channels c0 + 4e (e=0..7), fixed cell pos
        const float* pb = s_patch + c0 * P4;
#pragma unroll
        for (int e = 0; e < CHUNK_ELEMS / TPB; ++e) {   // 8
            float v = w00 * pb[o00] + w10 * pb[o10]
                    + w01 * pb[o01] + w11 * pb[o11];
            op[e * TPB] = v;
            pb += 4 * P4;
        }
        __syncthreads();   // patch reused next chunk

        fmc += CH * DD;
        op  += CHUNK_ELEMS;
    }
}

extern "C" void kernel_launch(void* const* d_in, const int* in_sizes, int n_in,
                              void* d_out, int out_size)
{
    const int N = in_sizes[0] / 4;
    roialign_banks_kernel<<<N, TPB>>>(
        (const float*)d_in[0],
        (const float*)d_in[1], (const float*)d_in[2], (const float*)d_in[3],
        (const float*)d_in[4], (const float*)d_in[5], (const float*)d_in[6],
        (float*)d_out);
}